// round 15
// baseline (speedup 1.0000x reference)
#include <cuda_runtime.h>
#include <cuda_bf16.h>
#include <cuda_fp16.h>
#include <cstdint>

#define N_NODES 100000
#define N_EDGES 3200000
#define F_IN 512
#define F_HID 64
#define F_OUT 20
#define SCAN_BLK 1024
#define N_SCANB ((N_NODES + SCAN_BLK - 1) / SCAN_BLK)  // 98

typedef unsigned long long u64;

// ---------------- scratch ----------------
__device__ __align__(256) float g_deg[N_NODES];
__device__ __align__(256) float g_dinv[N_NODES];
__device__ __align__(256) int g_cnt[N_NODES];
__device__ __align__(256) int g_rowstart[N_NODES];
__device__ __align__(256) int g_cursor[N_NODES];
__device__ __align__(256) int g_bsum[N_SCANB];
__device__ __align__(256) int g_boff[N_SCANB];
__device__ __align__(256) float2 g_edge[N_EDGES];        // (src bits, norm)
__device__ __align__(256) __half2 g_xw1h[N_NODES * 32];  // x @ W1, fp16 pairs
__device__ __align__(256) __half g_h2h[N_NODES * 32];    // relu(agg1) @ W2, fp16, stride 32

__device__ __forceinline__ uint32_t smem_u32(const void* p) {
    uint32_t a;
    asm("{ .reg .u64 t; cvta.to.shared.u64 t, %1; cvt.u32.u64 %0, t; }" : "=r"(a) : "l"(p));
    return a;
}

#define LDMATRIX_X4(r0, r1, r2, r3, addr)                                        \
    asm volatile("ldmatrix.sync.aligned.m8n8.x4.shared.b16 {%0,%1,%2,%3}, [%4];" \
                 : "=r"(r0), "=r"(r1), "=r"(r2), "=r"(r3) : "r"(addr))
#define LDMATRIX_X4_T(r0, r1, r2, r3, addr)                                            \
    asm volatile("ldmatrix.sync.aligned.m8n8.x4.trans.shared.b16 {%0,%1,%2,%3}, [%4];" \
                 : "=r"(r0), "=r"(r1), "=r"(r2), "=r"(r3) : "r"(addr))
#define MMA_BF16(c0, c1, c2, c3, a0, a1, a2, a3, b0, b1)                          \
    asm volatile(                                                                 \
        "mma.sync.aligned.m16n8k16.row.col.f32.bf16.bf16.f32 "                    \
        "{%0,%1,%2,%3}, {%4,%5,%6,%7}, {%8,%9}, {%0,%1,%2,%3};"                   \
        : "+f"(c0), "+f"(c1), "+f"(c2), "+f"(c3)                                  \
        : "r"(a0), "r"(a1), "r"(a2), "r"(a3), "r"(b0), "r"(b1))

// ---------------- GEMM1: xw1 = x @ W1, pure bf16 tensor cores, pipelined ----------------
#define A_STRIDE 40
#define B_STRIDE 72
#define N_KCHUNK (F_IN / 32)
__global__ __launch_bounds__(256, 2) void gemm1_tc_kernel(const float* __restrict__ x,
                                                          const float* __restrict__ W1) {
    __shared__ __nv_bfloat16 a_sm[128 * A_STRIDE];
    __shared__ __nv_bfloat16 b_sm[32 * B_STRIDE];

    const int tid = threadIdx.x;
    const int wid = tid >> 5;
    const int lane = tid & 31;
    const int nb = blockIdx.x * 128;

    float c[8][4];
#pragma unroll
    for (int j = 0; j < 8; j++)
#pragma unroll
        for (int q = 0; q < 4; q++) c[j][q] = 0.f;

    const int a_row = wid * 16 + (lane & 15);
    const int a_koff = (lane >> 4) * 8;
    const uint32_t a_addr = smem_u32(&a_sm[a_row * A_STRIDE + a_koff]);
    const int b_k = lane & 15;
    const int b_noff = (lane >> 4) * 8;
    const uint32_t b_base = smem_u32(&b_sm[b_k * B_STRIDE + b_noff]);

    const int ar[4] = {(tid + 0) >> 3, (tid + 256) >> 3, (tid + 512) >> 3, (tid + 768) >> 3};
    const int ac = (tid & 7) * 4;
    const int br[2] = {tid >> 4, (tid + 256) >> 4};
    const int bn = (tid & 15) * 4;

    float4 pa[4], pb[2];

#pragma unroll
    for (int j = 0; j < 4; j++) {
        int node = nb + ar[j];
        pa[j] = (node < N_NODES) ? *(const float4*)&x[(size_t)node * F_IN + ac]
                                 : make_float4(0.f, 0.f, 0.f, 0.f);
    }
#pragma unroll
    for (int j = 0; j < 2; j++) pb[j] = *(const float4*)&W1[(size_t)br[j] * F_HID + bn];

    for (int kc = 0; kc < N_KCHUNK; kc++) {
#pragma unroll
        for (int j = 0; j < 4; j++) {
            float4 v = pa[j];
            int r = ar[j];
            *(__nv_bfloat162*)&a_sm[r * A_STRIDE + ac] = __floats2bfloat162_rn(v.x, v.y);
            *(__nv_bfloat162*)&a_sm[r * A_STRIDE + ac + 2] = __floats2bfloat162_rn(v.z, v.w);
        }
#pragma unroll
        for (int j = 0; j < 2; j++) {
            float4 w = pb[j];
            int r = br[j];
            *(__nv_bfloat162*)&b_sm[r * B_STRIDE + bn] = __floats2bfloat162_rn(w.x, w.y);
            *(__nv_bfloat162*)&b_sm[r * B_STRIDE + bn + 2] = __floats2bfloat162_rn(w.z, w.w);
        }
        __syncthreads();

        if (kc + 1 < N_KCHUNK) {
            const int k0n = (kc + 1) * 32;
#pragma unroll
            for (int j = 0; j < 4; j++) {
                int node = nb + ar[j];
                pa[j] = (node < N_NODES) ? *(const float4*)&x[(size_t)node * F_IN + k0n + ac]
                                         : make_float4(0.f, 0.f, 0.f, 0.f);
            }
#pragma unroll
            for (int j = 0; j < 2; j++)
                pb[j] = *(const float4*)&W1[(size_t)(k0n + br[j]) * F_HID + bn];
        }

#pragma unroll
        for (int ks = 0; ks < 2; ks++) {
            uint32_t ah[4];
            LDMATRIX_X4(ah[0], ah[1], ah[2], ah[3], a_addr + ks * 32);
            uint32_t bh[4][4];
#pragma unroll
            for (int nf = 0; nf < 4; nf++) {
                LDMATRIX_X4_T(bh[nf][0], bh[nf][1], bh[nf][2], bh[nf][3],
                              b_base + ks * (16 * B_STRIDE * 2) + nf * 32);
            }
#pragma unroll
            for (int nf = 0; nf < 4; nf++) {
                MMA_BF16(c[2 * nf][0], c[2 * nf][1], c[2 * nf][2], c[2 * nf][3],
                         ah[0], ah[1], ah[2], ah[3], bh[nf][0], bh[nf][1]);
                MMA_BF16(c[2 * nf + 1][0], c[2 * nf + 1][1], c[2 * nf + 1][2], c[2 * nf + 1][3],
                         ah[0], ah[1], ah[2], ah[3], bh[nf][2], bh[nf][3]);
            }
        }
        __syncthreads();
    }

    const int g = lane >> 2;
    const int cl = (lane & 3) * 2;
    const int row0 = nb + wid * 16 + g;
    const int row1 = row0 + 8;
#pragma unroll
    for (int j = 0; j < 8; j++) {
        int col2 = (j * 8 + cl) >> 1;
        if (row0 < N_NODES) g_xw1h[(size_t)row0 * 32 + col2] = __floats2half2_rn(c[j][0], c[j][1]);
        if (row1 < N_NODES) g_xw1h[(size_t)row1 * 32 + col2] = __floats2half2_rn(c[j][2], c[j][3]);
    }
}

// ---------------- init ----------------
__global__ void init_kernel() {
    int i = blockIdx.x * blockDim.x + threadIdx.x;
    if (i < N_NODES) {
        g_deg[i] = 1.0f;
        g_cnt[i] = 0;
    }
}

// 4 edges per thread, vectorized
__global__ void deg_accum_kernel(const int* __restrict__ dst,
                                 const float* __restrict__ ew) {
    int t = blockIdx.x * blockDim.x + threadIdx.x;
    int e = t * 4;
    if (e + 4 <= N_EDGES) {
        int4 d4 = *(const int4*)&dst[e];
        float4 w4 = *(const float4*)&ew[e];
        atomicAdd(&g_deg[d4.x], w4.x);
        atomicAdd(&g_deg[d4.y], w4.y);
        atomicAdd(&g_deg[d4.z], w4.z);
        atomicAdd(&g_deg[d4.w], w4.w);
        atomicAdd(&g_cnt[d4.x], 1);
        atomicAdd(&g_cnt[d4.y], 1);
        atomicAdd(&g_cnt[d4.z], 1);
        atomicAdd(&g_cnt[d4.w], 1);
    } else {
        for (; e < N_EDGES; e++) {
            int d = dst[e];
            atomicAdd(&g_deg[d], ew[e]);
            atomicAdd(&g_cnt[d], 1);
        }
    }
}

// ---------------- scan ----------------
__global__ void scan1_kernel() {
    __shared__ int sh[SCAN_BLK];
    int i = blockIdx.x * SCAN_BLK + threadIdx.x;
    int t = threadIdx.x;
    int v = (i < N_NODES) ? g_cnt[i] : 0;
    sh[t] = v;
    __syncthreads();
#pragma unroll
    for (int off = 1; off < SCAN_BLK; off <<= 1) {
        int u = (t >= off) ? sh[t - off] : 0;
        __syncthreads();
        sh[t] += u;
        __syncthreads();
    }
    if (i < N_NODES) g_rowstart[i] = sh[t] - v;
    if (t == SCAN_BLK - 1) g_bsum[blockIdx.x] = sh[t];
}

__global__ void scan2_kernel() {
    __shared__ int sh[128];
    int t = threadIdx.x;
    int v = (t < N_SCANB) ? g_bsum[t] : 0;
    sh[t] = v;
    __syncthreads();
#pragma unroll
    for (int off = 1; off < 128; off <<= 1) {
        int u = (t >= off) ? sh[t - off] : 0;
        __syncthreads();
        sh[t] += u;
        __syncthreads();
    }
    if (t < N_SCANB) g_boff[t] = sh[t] - v;
}

// scan3 + dinv + cursor init fused
__global__ void scan3_kernel() {
    int i = blockIdx.x * blockDim.x + threadIdx.x;
    if (i < N_NODES) {
        int rs = g_rowstart[i] + g_boff[i / SCAN_BLK];
        g_rowstart[i] = rs;
        g_cursor[i] = rs;
        g_dinv[i] = rsqrtf(g_deg[i]);
    }
}

// 4 edges per thread, vectorized
__global__ void fill_kernel(const int* __restrict__ src, const int* __restrict__ dst,
                            const float* __restrict__ ew) {
    int t = blockIdx.x * blockDim.x + threadIdx.x;
    int e = t * 4;
    if (e + 4 <= N_EDGES) {
        int4 s4 = *(const int4*)&src[e];
        int4 d4 = *(const int4*)&dst[e];
        float4 w4 = *(const float4*)&ew[e];
        float ds[4] = {g_dinv[s4.x], g_dinv[s4.y], g_dinv[s4.z], g_dinv[s4.w]};
        float dd[4] = {g_dinv[d4.x], g_dinv[d4.y], g_dinv[d4.z], g_dinv[d4.w]};
        int sl[4];
        sl[0] = atomicAdd(&g_cursor[d4.x], 1);
        sl[1] = atomicAdd(&g_cursor[d4.y], 1);
        sl[2] = atomicAdd(&g_cursor[d4.z], 1);
        sl[3] = atomicAdd(&g_cursor[d4.w], 1);
        g_edge[sl[0]] = make_float2(__int_as_float(s4.x), ds[0] * w4.x * dd[0]);
        g_edge[sl[1]] = make_float2(__int_as_float(s4.y), ds[1] * w4.y * dd[1]);
        g_edge[sl[2]] = make_float2(__int_as_float(s4.z), ds[2] * w4.z * dd[2]);
        g_edge[sl[3]] = make_float2(__int_as_float(s4.w), ds[3] * w4.w * dd[3]);
    } else {
        for (; e < N_EDGES; e++) {
            int s = src[e];
            int d = dst[e];
            float nm = g_dinv[s] * ew[e] * g_dinv[d];
            int slot = atomicAdd(&g_cursor[d], 1);
            g_edge[slot] = make_float2(__int_as_float(s), nm);
        }
    }
}

// ---------------- agg1 + gemm2 fused: 8 warps = 8 nodes per block, MLP-16 ----------------
__global__ __launch_bounds__(256) void agg1_gemm2_kernel(const float* __restrict__ b1,
                                                         const float* __restrict__ W2) {
    __shared__ float hs[8][68];
    __shared__ float ws[64][20];
    const int tid = threadIdx.x;
    const int w = tid >> 5;
    const int lane = tid & 31;
    const int n = blockIdx.x * 8 + w;

#pragma unroll
    for (int i = tid; i < 64 * 20; i += 256) ws[i / 20][i % 20] = W2[i];

    if (n < N_NODES) {
        int i = g_rowstart[n];
        int end = i + g_cnt[n];
        float2 acc = make_float2(0.f, 0.f);
        for (; i + 16 <= end; i += 16) {
            float2 e[16];
#pragma unroll
            for (int j = 0; j < 16; j++) e[j] = g_edge[i + j];
            float2 v[16];
#pragma unroll
            for (int j = 0; j < 16; j++)
                v[j] = __half22float2(g_xw1h[(size_t)__float_as_int(e[j].x) * 32 + lane]);
#pragma unroll
            for (int j = 0; j < 16; j++) {
                acc.x = fmaf(e[j].y, v[j].x, acc.x);
                acc.y = fmaf(e[j].y, v[j].y, acc.y);
            }
        }
        for (; i + 4 <= end; i += 4) {
            float2 e[4];
#pragma unroll
            for (int j = 0; j < 4; j++) e[j] = g_edge[i + j];
            float2 v[4];
#pragma unroll
            for (int j = 0; j < 4; j++)
                v[j] = __half22float2(g_xw1h[(size_t)__float_as_int(e[j].x) * 32 + lane]);
#pragma unroll
            for (int j = 0; j < 4; j++) {
                acc.x = fmaf(e[j].y, v[j].x, acc.x);
                acc.y = fmaf(e[j].y, v[j].y, acc.y);
            }
        }
        for (; i < end; i++) {
            float2 ep = g_edge[i];
            float2 v = __half22float2(g_xw1h[(size_t)__float_as_int(ep.x) * 32 + lane]);
            acc.x = fmaf(ep.y, v.x, acc.x);
            acc.y = fmaf(ep.y, v.y, acc.y);
        }
        float di = g_dinv[n];
        float dd = di * di;
        float2 xv = __half22float2(g_xw1h[(size_t)n * 32 + lane]);
        float2 bv = *(const float2*)&b1[lane * 2];
        hs[w][lane * 2] = fmaxf(bv.x + dd * xv.x + acc.x, 0.f);
        hs[w][lane * 2 + 1] = fmaxf(bv.y + dd * xv.y + acc.y, 0.f);
    }
    __syncthreads();

    if (tid < 160) {
        int nn = tid / 20;
        int o = tid % 20;
        int node = blockIdx.x * 8 + nn;
        if (node < N_NODES) {
            float acc = 0.f;
#pragma unroll
            for (int k = 0; k < 64; k++) acc = fmaf(hs[nn][k], ws[k][o], acc);
            g_h2h[(size_t)node * 32 + o] = __float2half(acc);
        }
    }
}

// ---------------- agg2 + softmax, MLP-16 ----------------
__global__ __launch_bounds__(256) void agg2_kernel(const float* __restrict__ b2,
                                                   float* __restrict__ out) {
    int warp = (blockIdx.x * blockDim.x + threadIdx.x) >> 5;
    int lane = threadIdx.x & 31;
    if (warp >= N_NODES) return;
    int n = warp;
    int i = g_rowstart[n];
    int end = i + g_cnt[n];
    int col = (lane < F_OUT) ? lane : 0;
    float acc = 0.f;
    for (; i + 16 <= end; i += 16) {
        float2 e[16];
#pragma unroll
        for (int j = 0; j < 16; j++) e[j] = g_edge[i + j];
        float v[16];
#pragma unroll
        for (int j = 0; j < 16; j++)
            v[j] = __half2float(g_h2h[(size_t)__float_as_int(e[j].x) * 32 + col]);
#pragma unroll
        for (int j = 0; j < 16; j++) acc = fmaf(e[j].y, v[j], acc);
    }
    for (; i + 4 <= end; i += 4) {
        float2 e[4];
#pragma unroll
        for (int j = 0; j < 4; j++) e[j] = g_edge[i + j];
        float v[4];
#pragma unroll
        for (int j = 0; j < 4; j++)
            v[j] = __half2float(g_h2h[(size_t)__float_as_int(e[j].x) * 32 + col]);
#pragma unroll
        for (int j = 0; j < 4; j++) acc = fmaf(e[j].y, v[j], acc);
    }
    for (; i < end; i++) {
        float2 ep = g_edge[i];
        acc = fmaf(ep.y, __half2float(g_h2h[(size_t)__float_as_int(ep.x) * 32 + col]), acc);
    }
    float di = g_dinv[n];
    float dd = di * di;
    float val = -1e30f;
    if (lane < F_OUT)
        val = b2[lane] + dd * __half2float(g_h2h[(size_t)n * 32 + lane]) + acc;
    float m = val;
#pragma unroll
    for (int o = 16; o > 0; o >>= 1) m = fmaxf(m, __shfl_xor_sync(0xFFFFFFFF, m, o));
    float ex = (lane < F_OUT) ? __expf(val - m) : 0.f;
    float s = ex;
#pragma unroll
    for (int o = 16; o > 0; o >>= 1) s += __shfl_xor_sync(0xFFFFFFFF, s, o);
    if (lane < F_OUT) out[(size_t)n * F_OUT + lane] = ex / s;
}

// ---------------- launch ----------------
extern "C" void kernel_launch(void* const* d_in, const int* in_sizes, int n_in,
                              void* d_out, int out_size) {
    const float* x = (const float*)d_in[0];
    const int* ei = (const int*)d_in[1];
    const float* ew = (const float*)d_in[2];
    const float* W1 = (const float*)d_in[3];
    const float* b1 = (const float*)d_in[4];
    const float* W2 = (const float*)d_in[5];
    const float* b2 = (const float*)d_in[6];
    float* out = (float*)d_out;

    const int* src = ei;
    const int* dst = ei + N_EDGES;

    // one-time infra (created on the uncaptured correctness call; reused during capture)
    static cudaStream_t s2 = nullptr;
    static cudaEvent_t ev_fork = nullptr, ev_join = nullptr;
    if (s2 == nullptr) {
        cudaStreamCreateWithFlags(&s2, cudaStreamNonBlocking);
        cudaEventCreateWithFlags(&ev_fork, cudaEventDisableTiming);
        cudaEventCreateWithFlags(&ev_join, cudaEventDisableTiming);
    }

    // fork: gemm1 on s2, overlapped with the CSR pre-pass on the main stream
    cudaEventRecord(ev_fork, 0);
    cudaStreamWaitEvent(s2, ev_fork, 0);
    gemm1_tc_kernel<<<(N_NODES + 127) / 128, 256, 0, s2>>>(x, W1);
    cudaEventRecord(ev_join, s2);

    // pre-pass chain (main stream)
    init_kernel<<<(N_NODES + 255) / 256, 256>>>();
    deg_accum_kernel<<<(N_EDGES / 4 + 255) / 256, 256>>>(dst, ew);
    scan1_kernel<<<N_SCANB, SCAN_BLK>>>();
    scan2_kernel<<<1, 128>>>();
    scan3_kernel<<<(N_NODES + 255) / 256, 256>>>();
    fill_kernel<<<(N_EDGES / 4 + 255) / 256, 256>>>(src, dst, ew);

    // join: agg1 needs both fill (main) and gemm1 (s2)
    cudaStreamWaitEvent(0, ev_join, 0);
    agg1_gemm2_kernel<<<(N_NODES + 7) / 8, 256>>>(b1, W2);
    agg2_kernel<<<(N_NODES * 32 + 255) / 256, 256>>>(b2, out);
}

// round 16
// speedup vs baseline: 1.0102x; 1.0102x over previous
#include <cuda_runtime.h>
#include <cuda_bf16.h>
#include <cuda_fp16.h>
#include <cstdint>

#define N_NODES 100000
#define N_EDGES 3200000
#define F_IN 512
#define F_HID 64
#define F_OUT 20
#define SCAN_BLK 1024
#define N_SCANB ((N_NODES + SCAN_BLK - 1) / SCAN_BLK)  // 98

typedef unsigned long long u64;

// ---------------- scratch ----------------
__device__ __align__(256) float g_deg[N_NODES];
__device__ __align__(256) float g_dinv[N_NODES];
__device__ __align__(256) int g_cnt[N_NODES];
__device__ __align__(256) int g_rowstart[N_NODES];
__device__ __align__(256) int g_cursor[N_NODES];
__device__ __align__(256) int g_bsum[N_SCANB];
__device__ __align__(256) int g_boff[N_SCANB];
__device__ __align__(256) float2 g_edge[N_EDGES + 8];    // (src bits, norm), padded for f4 tail
__device__ __align__(256) __half2 g_xw1h[N_NODES * 32];  // x @ W1, fp16 pairs
__device__ __align__(256) __half g_h2h[N_NODES * 32];    // relu(agg1) @ W2, fp16, stride 32

__device__ __forceinline__ uint32_t smem_u32(const void* p) {
    uint32_t a;
    asm("{ .reg .u64 t; cvta.to.shared.u64 t, %1; cvt.u32.u64 %0, t; }" : "=r"(a) : "l"(p));
    return a;
}

#define LDMATRIX_X4(r0, r1, r2, r3, addr)                                        \
    asm volatile("ldmatrix.sync.aligned.m8n8.x4.shared.b16 {%0,%1,%2,%3}, [%4];" \
                 : "=r"(r0), "=r"(r1), "=r"(r2), "=r"(r3) : "r"(addr))
#define LDMATRIX_X4_T(r0, r1, r2, r3, addr)                                            \
    asm volatile("ldmatrix.sync.aligned.m8n8.x4.trans.shared.b16 {%0,%1,%2,%3}, [%4];" \
                 : "=r"(r0), "=r"(r1), "=r"(r2), "=r"(r3) : "r"(addr))
#define MMA_BF16(c0, c1, c2, c3, a0, a1, a2, a3, b0, b1)                          \
    asm volatile(                                                                 \
        "mma.sync.aligned.m16n8k16.row.col.f32.bf16.bf16.f32 "                    \
        "{%0,%1,%2,%3}, {%4,%5,%6,%7}, {%8,%9}, {%0,%1,%2,%3};"                   \
        : "+f"(c0), "+f"(c1), "+f"(c2), "+f"(c3)                                  \
        : "r"(a0), "r"(a1), "r"(a2), "r"(a3), "r"(b0), "r"(b1))

// ---------------- GEMM1: xw1 = x @ W1, pure bf16 tensor cores, pipelined ----------------
#define A_STRIDE 40
#define B_STRIDE 72
#define N_KCHUNK (F_IN / 32)
__global__ __launch_bounds__(256, 2) void gemm1_tc_kernel(const float* __restrict__ x,
                                                          const float* __restrict__ W1) {
    __shared__ __nv_bfloat16 a_sm[128 * A_STRIDE];
    __shared__ __nv_bfloat16 b_sm[32 * B_STRIDE];

    const int tid = threadIdx.x;
    const int wid = tid >> 5;
    const int lane = tid & 31;
    const int nb = blockIdx.x * 128;

    float c[8][4];
#pragma unroll
    for (int j = 0; j < 8; j++)
#pragma unroll
        for (int q = 0; q < 4; q++) c[j][q] = 0.f;

    const int a_row = wid * 16 + (lane & 15);
    const int a_koff = (lane >> 4) * 8;
    const uint32_t a_addr = smem_u32(&a_sm[a_row * A_STRIDE + a_koff]);
    const int b_k = lane & 15;
    const int b_noff = (lane >> 4) * 8;
    const uint32_t b_base = smem_u32(&b_sm[b_k * B_STRIDE + b_noff]);

    const int ar[4] = {(tid + 0) >> 3, (tid + 256) >> 3, (tid + 512) >> 3, (tid + 768) >> 3};
    const int ac = (tid & 7) * 4;
    const int br[2] = {tid >> 4, (tid + 256) >> 4};
    const int bn = (tid & 15) * 4;

    float4 pa[4], pb[2];

#pragma unroll
    for (int j = 0; j < 4; j++) {
        int node = nb + ar[j];
        pa[j] = (node < N_NODES) ? *(const float4*)&x[(size_t)node * F_IN + ac]
                                 : make_float4(0.f, 0.f, 0.f, 0.f);
    }
#pragma unroll
    for (int j = 0; j < 2; j++) pb[j] = *(const float4*)&W1[(size_t)br[j] * F_HID + bn];

    for (int kc = 0; kc < N_KCHUNK; kc++) {
#pragma unroll
        for (int j = 0; j < 4; j++) {
            float4 v = pa[j];
            int r = ar[j];
            *(__nv_bfloat162*)&a_sm[r * A_STRIDE + ac] = __floats2bfloat162_rn(v.x, v.y);
            *(__nv_bfloat162*)&a_sm[r * A_STRIDE + ac + 2] = __floats2bfloat162_rn(v.z, v.w);
        }
#pragma unroll
        for (int j = 0; j < 2; j++) {
            float4 w = pb[j];
            int r = br[j];
            *(__nv_bfloat162*)&b_sm[r * B_STRIDE + bn] = __floats2bfloat162_rn(w.x, w.y);
            *(__nv_bfloat162*)&b_sm[r * B_STRIDE + bn + 2] = __floats2bfloat162_rn(w.z, w.w);
        }
        __syncthreads();

        if (kc + 1 < N_KCHUNK) {
            const int k0n = (kc + 1) * 32;
#pragma unroll
            for (int j = 0; j < 4; j++) {
                int node = nb + ar[j];
                pa[j] = (node < N_NODES) ? *(const float4*)&x[(size_t)node * F_IN + k0n + ac]
                                         : make_float4(0.f, 0.f, 0.f, 0.f);
            }
#pragma unroll
            for (int j = 0; j < 2; j++)
                pb[j] = *(const float4*)&W1[(size_t)(k0n + br[j]) * F_HID + bn];
        }

#pragma unroll
        for (int ks = 0; ks < 2; ks++) {
            uint32_t ah[4];
            LDMATRIX_X4(ah[0], ah[1], ah[2], ah[3], a_addr + ks * 32);
            uint32_t bh[4][4];
#pragma unroll
            for (int nf = 0; nf < 4; nf++) {
                LDMATRIX_X4_T(bh[nf][0], bh[nf][1], bh[nf][2], bh[nf][3],
                              b_base + ks * (16 * B_STRIDE * 2) + nf * 32);
            }
#pragma unroll
            for (int nf = 0; nf < 4; nf++) {
                MMA_BF16(c[2 * nf][0], c[2 * nf][1], c[2 * nf][2], c[2 * nf][3],
                         ah[0], ah[1], ah[2], ah[3], bh[nf][0], bh[nf][1]);
                MMA_BF16(c[2 * nf + 1][0], c[2 * nf + 1][1], c[2 * nf + 1][2], c[2 * nf + 1][3],
                         ah[0], ah[1], ah[2], ah[3], bh[nf][2], bh[nf][3]);
            }
        }
        __syncthreads();
    }

    const int g = lane >> 2;
    const int cl = (lane & 3) * 2;
    const int row0 = nb + wid * 16 + g;
    const int row1 = row0 + 8;
#pragma unroll
    for (int j = 0; j < 8; j++) {
        int col2 = (j * 8 + cl) >> 1;
        if (row0 < N_NODES) g_xw1h[(size_t)row0 * 32 + col2] = __floats2half2_rn(c[j][0], c[j][1]);
        if (row1 < N_NODES) g_xw1h[(size_t)row1 * 32 + col2] = __floats2half2_rn(c[j][2], c[j][3]);
    }
}

// ---------------- init ----------------
__global__ void init_kernel() {
    int i = blockIdx.x * blockDim.x + threadIdx.x;
    if (i < N_NODES) {
        g_deg[i] = 1.0f;
        g_cnt[i] = 0;
    }
}

__global__ void deg_accum_kernel(const int* __restrict__ dst,
                                 const float* __restrict__ ew) {
    int e = blockIdx.x * blockDim.x + threadIdx.x;
    if (e < N_EDGES) {
        int d = dst[e];
        atomicAdd(&g_deg[d], ew[e]);
        atomicAdd(&g_cnt[d], 1);
    }
}

// ---------------- scan ----------------
__global__ void scan1_kernel() {
    __shared__ int sh[SCAN_BLK];
    int i = blockIdx.x * SCAN_BLK + threadIdx.x;
    int t = threadIdx.x;
    int v = (i < N_NODES) ? g_cnt[i] : 0;
    sh[t] = v;
    __syncthreads();
#pragma unroll
    for (int off = 1; off < SCAN_BLK; off <<= 1) {
        int u = (t >= off) ? sh[t - off] : 0;
        __syncthreads();
        sh[t] += u;
        __syncthreads();
    }
    if (i < N_NODES) g_rowstart[i] = sh[t] - v;
    if (t == SCAN_BLK - 1) g_bsum[blockIdx.x] = sh[t];
}

__global__ void scan2_kernel() {
    __shared__ int sh[128];
    int t = threadIdx.x;
    int v = (t < N_SCANB) ? g_bsum[t] : 0;
    sh[t] = v;
    __syncthreads();
#pragma unroll
    for (int off = 1; off < 128; off <<= 1) {
        int u = (t >= off) ? sh[t - off] : 0;
        __syncthreads();
        sh[t] += u;
        __syncthreads();
    }
    if (t < N_SCANB) g_boff[t] = sh[t] - v;
}

// scan3 + dinv + cursor init fused
__global__ void scan3_kernel() {
    int i = blockIdx.x * blockDim.x + threadIdx.x;
    if (i < N_NODES) {
        int rs = g_rowstart[i] + g_boff[i / SCAN_BLK];
        g_rowstart[i] = rs;
        g_cursor[i] = rs;
        g_dinv[i] = rsqrtf(g_deg[i]);
    }
}

__global__ void fill_kernel(const int* __restrict__ src, const int* __restrict__ dst,
                            const float* __restrict__ ew) {
    int e = blockIdx.x * blockDim.x + threadIdx.x;
    if (e >= N_EDGES) return;
    int s = src[e];
    int d = dst[e];
    float nm = g_dinv[s] * ew[e] * g_dinv[d];
    int slot = atomicAdd(&g_cursor[d], 1);
    g_edge[slot] = make_float2(__int_as_float(s), nm);
}

// ---------------- agg1 + gemm2 fused: 8 warps = 8 nodes per block ----------------
// edge loads: float4 = 2 edges per LDG; gathers MLP-8.
__global__ __launch_bounds__(256) void agg1_gemm2_kernel(const float* __restrict__ b1,
                                                         const float* __restrict__ W2) {
    __shared__ float hs[8][68];
    __shared__ float ws[64][20];
    const int tid = threadIdx.x;
    const int w = tid >> 5;
    const int lane = tid & 31;
    const int n = blockIdx.x * 8 + w;

#pragma unroll
    for (int i = tid; i < 64 * 20; i += 256) ws[i / 20][i % 20] = W2[i];

    if (n < N_NODES) {
        int i = g_rowstart[n];
        const int end = i + g_cnt[n];
        float2 acc = make_float2(0.f, 0.f);
        // scalar head to even alignment
        if ((i & 1) && i < end) {
            float2 ep = g_edge[i];
            float2 v = __half22float2(g_xw1h[(size_t)__float_as_int(ep.x) * 32 + lane]);
            acc.x = fmaf(ep.y, v.x, acc.x);
            acc.y = fmaf(ep.y, v.y, acc.y);
            i++;
        }
        // 8 edges per iter: 4 float4 loads + 8 gathers
        for (; i + 8 <= end; i += 8) {
            float4 q[4];
#pragma unroll
            for (int j = 0; j < 4; j++) q[j] = *(const float4*)&g_edge[i + j * 2];
            float2 v[8];
#pragma unroll
            for (int j = 0; j < 4; j++) {
                v[2 * j] = __half22float2(g_xw1h[(size_t)__float_as_int(q[j].x) * 32 + lane]);
                v[2 * j + 1] = __half22float2(g_xw1h[(size_t)__float_as_int(q[j].z) * 32 + lane]);
            }
#pragma unroll
            for (int j = 0; j < 4; j++) {
                acc.x = fmaf(q[j].y, v[2 * j].x, acc.x);
                acc.y = fmaf(q[j].y, v[2 * j].y, acc.y);
                acc.x = fmaf(q[j].w, v[2 * j + 1].x, acc.x);
                acc.y = fmaf(q[j].w, v[2 * j + 1].y, acc.y);
            }
        }
        for (; i < end; i++) {
            float2 ep = g_edge[i];
            float2 v = __half22float2(g_xw1h[(size_t)__float_as_int(ep.x) * 32 + lane]);
            acc.x = fmaf(ep.y, v.x, acc.x);
            acc.y = fmaf(ep.y, v.y, acc.y);
        }
        float di = g_dinv[n];
        float dd = di * di;
        float2 xv = __half22float2(g_xw1h[(size_t)n * 32 + lane]);
        float2 bv = *(const float2*)&b1[lane * 2];
        hs[w][lane * 2] = fmaxf(bv.x + dd * xv.x + acc.x, 0.f);
        hs[w][lane * 2 + 1] = fmaxf(bv.y + dd * xv.y + acc.y, 0.f);
    }
    __syncthreads();

    if (tid < 160) {
        int nn = tid / 20;
        int o = tid % 20;
        int node = blockIdx.x * 8 + nn;
        if (node < N_NODES) {
            float acc = 0.f;
#pragma unroll
            for (int k = 0; k < 64; k++) acc = fmaf(hs[nn][k], ws[k][o], acc);
            g_h2h[(size_t)node * 32 + o] = __float2half(acc);
        }
    }
}

// ---------------- agg2 + softmax: float4 edge loads, gathers MLP-8 ----------------
__global__ __launch_bounds__(256) void agg2_kernel(const float* __restrict__ b2,
                                                   float* __restrict__ out) {
    int warp = (blockIdx.x * blockDim.x + threadIdx.x) >> 5;
    int lane = threadIdx.x & 31;
    if (warp >= N_NODES) return;
    int n = warp;
    int i = g_rowstart[n];
    const int end = i + g_cnt[n];
    int col = (lane < F_OUT) ? lane : 0;
    float acc = 0.f;
    if ((i & 1) && i < end) {
        float2 ep = g_edge[i];
        acc = fmaf(ep.y, __half2float(g_h2h[(size_t)__float_as_int(ep.x) * 32 + col]), acc);
        i++;
    }
    for (; i + 8 <= end; i += 8) {
        float4 q[4];
#pragma unroll
        for (int j = 0; j < 4; j++) q[j] = *(const float4*)&g_edge[i + j * 2];
        float v[8];
#pragma unroll
        for (int j = 0; j < 4; j++) {
            v[2 * j] = __half2float(g_h2h[(size_t)__float_as_int(q[j].x) * 32 + col]);
            v[2 * j + 1] = __half2float(g_h2h[(size_t)__float_as_int(q[j].z) * 32 + col]);
        }
#pragma unroll
        for (int j = 0; j < 4; j++) {
            acc = fmaf(q[j].y, v[2 * j], acc);
            acc = fmaf(q[j].w, v[2 * j + 1], acc);
        }
    }
    for (; i < end; i++) {
        float2 ep = g_edge[i];
        acc = fmaf(ep.y, __half2float(g_h2h[(size_t)__float_as_int(ep.x) * 32 + col]), acc);
    }
    float di = g_dinv[n];
    float dd = di * di;
    float val = -1e30f;
    if (lane < F_OUT)
        val = b2[lane] + dd * __half2float(g_h2h[(size_t)n * 32 + lane]) + acc;
    float m = val;
#pragma unroll
    for (int o = 16; o > 0; o >>= 1) m = fmaxf(m, __shfl_xor_sync(0xFFFFFFFF, m, o));
    float ex = (lane < F_OUT) ? __expf(val - m) : 0.f;
    float s = ex;
#pragma unroll
    for (int o = 16; o > 0; o >>= 1) s += __shfl_xor_sync(0xFFFFFFFF, s, o);
    if (lane < F_OUT) out[(size_t)n * F_OUT + lane] = ex / s;
}

// ---------------- launch ----------------
extern "C" void kernel_launch(void* const* d_in, const int* in_sizes, int n_in,
                              void* d_out, int out_size) {
    const float* x = (const float*)d_in[0];
    const int* ei = (const int*)d_in[1];
    const float* ew = (const float*)d_in[2];
    const float* W1 = (const float*)d_in[3];
    const float* b1 = (const float*)d_in[4];
    const float* W2 = (const float*)d_in[5];
    const float* b2 = (const float*)d_in[6];
    float* out = (float*)d_out;

    const int* src = ei;
    const int* dst = ei + N_EDGES;

    // one-time infra (created on the uncaptured correctness call; reused during capture)
    static cudaStream_t s2 = nullptr;
    static cudaEvent_t ev_fork = nullptr, ev_join = nullptr;
    if (s2 == nullptr) {
        cudaStreamCreateWithFlags(&s2, cudaStreamNonBlocking);
        cudaEventCreateWithFlags(&ev_fork, cudaEventDisableTiming);
        cudaEventCreateWithFlags(&ev_join, cudaEventDisableTiming);
    }

    // fork: gemm1 on s2, overlapped with the CSR pre-pass on the main stream
    cudaEventRecord(ev_fork, 0);
    cudaStreamWaitEvent(s2, ev_fork, 0);
    gemm1_tc_kernel<<<(N_NODES + 127) / 128, 256, 0, s2>>>(x, W1);
    cudaEventRecord(ev_join, s2);

    // pre-pass chain (main stream)
    init_kernel<<<(N_NODES + 255) / 256, 256>>>();
    deg_accum_kernel<<<(N_EDGES + 255) / 256, 256>>>(dst, ew);
    scan1_kernel<<<N_SCANB, SCAN_BLK>>>();
    scan2_kernel<<<1, 128>>>();
    scan3_kernel<<<(N_NODES + 255) / 256, 256>>>();
    fill_kernel<<<(N_EDGES + 255) / 256, 256>>>(src, dst, ew);

    // join: agg1 needs both fill (main) and gemm1 (s2)
    cudaStreamWaitEvent(0, ev_join, 0);
    agg1_gemm2_kernel<<<(N_NODES + 7) / 8, 256>>>(b1, W2);
    agg2_kernel<<<(N_NODES * 32 + 255) / 256, 256>>>(b2, out);
}

// round 17
// speedup vs baseline: 1.0556x; 1.0450x over previous
#include <cuda_runtime.h>
#include <cuda_bf16.h>
#include <cuda_fp16.h>
#include <cstdint>

#define N_NODES 100000
#define N_EDGES 3200000
#define F_IN 512
#define F_HID 64
#define F_OUT 20
#define SCAN_BLK 1024
#define N_SCANB ((N_NODES + SCAN_BLK - 1) / SCAN_BLK)  // 98

typedef unsigned long long u64;

// ---------------- scratch ----------------
__device__ __align__(256) u64 g_pack[N_NODES];  // (deg_fixed<<20) | cnt
__device__ __align__(256) float g_dinv[N_NODES];
__device__ __align__(256) int g_cnt[N_NODES];
__device__ __align__(256) int g_rowstart[N_NODES];
__device__ __align__(256) int g_cursor[N_NODES];
__device__ __align__(256) int g_bsum[N_SCANB];
__device__ __align__(256) int g_boff[N_SCANB];
__device__ __align__(256) float2 g_edge[N_EDGES];        // (src bits, norm)
__device__ __align__(256) __half2 g_xw1h[N_NODES * 32];  // x @ W1, fp16 pairs
__device__ __align__(256) __half g_h2h[N_NODES * 32];    // relu(agg1) @ W2, fp16, stride 32

__device__ __forceinline__ uint32_t smem_u32(const void* p) {
    uint32_t a;
    asm("{ .reg .u64 t; cvta.to.shared.u64 t, %1; cvt.u32.u64 %0, t; }" : "=r"(a) : "l"(p));
    return a;
}

#define LDMATRIX_X4(r0, r1, r2, r3, addr)                                        \
    asm volatile("ldmatrix.sync.aligned.m8n8.x4.shared.b16 {%0,%1,%2,%3}, [%4];" \
                 : "=r"(r0), "=r"(r1), "=r"(r2), "=r"(r3) : "r"(addr))
#define LDMATRIX_X4_T(r0, r1, r2, r3, addr)                                            \
    asm volatile("ldmatrix.sync.aligned.m8n8.x4.trans.shared.b16 {%0,%1,%2,%3}, [%4];" \
                 : "=r"(r0), "=r"(r1), "=r"(r2), "=r"(r3) : "r"(addr))
#define MMA_BF16(c0, c1, c2, c3, a0, a1, a2, a3, b0, b1)                          \
    asm volatile(                                                                 \
        "mma.sync.aligned.m16n8k16.row.col.f32.bf16.bf16.f32 "                    \
        "{%0,%1,%2,%3}, {%4,%5,%6,%7}, {%8,%9}, {%0,%1,%2,%3};"                   \
        : "+f"(c0), "+f"(c1), "+f"(c2), "+f"(c3)                                  \
        : "r"(a0), "r"(a1), "r"(a2), "r"(a3), "r"(b0), "r"(b1))

// ---------------- GEMM1: xw1 = x @ W1, pure bf16 tensor cores, pipelined ----------------
#define A_STRIDE 40
#define B_STRIDE 72
#define N_KCHUNK (F_IN / 32)
__global__ __launch_bounds__(256, 2) void gemm1_tc_kernel(const float* __restrict__ x,
                                                          const float* __restrict__ W1) {
    __shared__ __nv_bfloat16 a_sm[128 * A_STRIDE];
    __shared__ __nv_bfloat16 b_sm[32 * B_STRIDE];

    const int tid = threadIdx.x;
    const int wid = tid >> 5;
    const int lane = tid & 31;
    const int nb = blockIdx.x * 128;

    float c[8][4];
#pragma unroll
    for (int j = 0; j < 8; j++)
#pragma unroll
        for (int q = 0; q < 4; q++) c[j][q] = 0.f;

    const int a_row = wid * 16 + (lane & 15);
    const int a_koff = (lane >> 4) * 8;
    const uint32_t a_addr = smem_u32(&a_sm[a_row * A_STRIDE + a_koff]);
    const int b_k = lane & 15;
    const int b_noff = (lane >> 4) * 8;
    const uint32_t b_base = smem_u32(&b_sm[b_k * B_STRIDE + b_noff]);

    const int ar[4] = {(tid + 0) >> 3, (tid + 256) >> 3, (tid + 512) >> 3, (tid + 768) >> 3};
    const int ac = (tid & 7) * 4;
    const int br[2] = {tid >> 4, (tid + 256) >> 4};
    const int bn = (tid & 15) * 4;

    float4 pa[4], pb[2];

#pragma unroll
    for (int j = 0; j < 4; j++) {
        int node = nb + ar[j];
        pa[j] = (node < N_NODES) ? *(const float4*)&x[(size_t)node * F_IN + ac]
                                 : make_float4(0.f, 0.f, 0.f, 0.f);
    }
#pragma unroll
    for (int j = 0; j < 2; j++) pb[j] = *(const float4*)&W1[(size_t)br[j] * F_HID + bn];

    for (int kc = 0; kc < N_KCHUNK; kc++) {
#pragma unroll
        for (int j = 0; j < 4; j++) {
            float4 v = pa[j];
            int r = ar[j];
            *(__nv_bfloat162*)&a_sm[r * A_STRIDE + ac] = __floats2bfloat162_rn(v.x, v.y);
            *(__nv_bfloat162*)&a_sm[r * A_STRIDE + ac + 2] = __floats2bfloat162_rn(v.z, v.w);
        }
#pragma unroll
        for (int j = 0; j < 2; j++) {
            float4 w = pb[j];
            int r = br[j];
            *(__nv_bfloat162*)&b_sm[r * B_STRIDE + bn] = __floats2bfloat162_rn(w.x, w.y);
            *(__nv_bfloat162*)&b_sm[r * B_STRIDE + bn + 2] = __floats2bfloat162_rn(w.z, w.w);
        }
        __syncthreads();

        if (kc + 1 < N_KCHUNK) {
            const int k0n = (kc + 1) * 32;
#pragma unroll
            for (int j = 0; j < 4; j++) {
                int node = nb + ar[j];
                pa[j] = (node < N_NODES) ? *(const float4*)&x[(size_t)node * F_IN + k0n + ac]
                                         : make_float4(0.f, 0.f, 0.f, 0.f);
            }
#pragma unroll
            for (int j = 0; j < 2; j++)
                pb[j] = *(const float4*)&W1[(size_t)(k0n + br[j]) * F_HID + bn];
        }

#pragma unroll
        for (int ks = 0; ks < 2; ks++) {
            uint32_t ah[4];
            LDMATRIX_X4(ah[0], ah[1], ah[2], ah[3], a_addr + ks * 32);
            uint32_t bh[4][4];
#pragma unroll
            for (int nf = 0; nf < 4; nf++) {
                LDMATRIX_X4_T(bh[nf][0], bh[nf][1], bh[nf][2], bh[nf][3],
                              b_base + ks * (16 * B_STRIDE * 2) + nf * 32);
            }
#pragma unroll
            for (int nf = 0; nf < 4; nf++) {
                MMA_BF16(c[2 * nf][0], c[2 * nf][1], c[2 * nf][2], c[2 * nf][3],
                         ah[0], ah[1], ah[2], ah[3], bh[nf][0], bh[nf][1]);
                MMA_BF16(c[2 * nf + 1][0], c[2 * nf + 1][1], c[2 * nf + 1][2], c[2 * nf + 1][3],
                         ah[0], ah[1], ah[2], ah[3], bh[nf][2], bh[nf][3]);
            }
        }
        __syncthreads();
    }

    const int g = lane >> 2;
    const int cl = (lane & 3) * 2;
    const int row0 = nb + wid * 16 + g;
    const int row1 = row0 + 8;
#pragma unroll
    for (int j = 0; j < 8; j++) {
        int col2 = (j * 8 + cl) >> 1;
        if (row0 < N_NODES) g_xw1h[(size_t)row0 * 32 + col2] = __floats2half2_rn(c[j][0], c[j][1]);
        if (row1 < N_NODES) g_xw1h[(size_t)row1 * 32 + col2] = __floats2half2_rn(c[j][2], c[j][3]);
    }
}

// ---------------- init ----------------
__global__ void init_kernel() {
    int i = blockIdx.x * blockDim.x + threadIdx.x;
    if (i < N_NODES) g_pack[i] = 0ull;
}

// single packed u64 atomic per edge: deg (fixed 2^-24) + cnt
__global__ void deg_accum_kernel(const int* __restrict__ dst,
                                 const float* __restrict__ ew) {
    int e = blockIdx.x * blockDim.x + threadIdx.x;
    if (e < N_EDGES) {
        int d = dst[e];
        u64 v = ((u64)__float2ll_rn(ew[e] * 16777216.0f) << 20) | 1ull;
        atomicAdd(&g_pack[d], v);
    }
}

// ---------------- scan ----------------
__global__ void scan1_kernel() {
    __shared__ int sh[SCAN_BLK];
    int i = blockIdx.x * SCAN_BLK + threadIdx.x;
    int t = threadIdx.x;
    int v = (i < N_NODES) ? (int)(g_pack[i] & 0xFFFFFull) : 0;
    sh[t] = v;
    __syncthreads();
#pragma unroll
    for (int off = 1; off < SCAN_BLK; off <<= 1) {
        int u = (t >= off) ? sh[t - off] : 0;
        __syncthreads();
        sh[t] += u;
        __syncthreads();
    }
    if (i < N_NODES) {
        g_rowstart[i] = sh[t] - v;
        g_cnt[i] = v;
    }
    if (t == SCAN_BLK - 1) g_bsum[blockIdx.x] = sh[t];
}

__global__ void scan2_kernel() {
    __shared__ int sh[128];
    int t = threadIdx.x;
    int v = (t < N_SCANB) ? g_bsum[t] : 0;
    sh[t] = v;
    __syncthreads();
#pragma unroll
    for (int off = 1; off < 128; off <<= 1) {
        int u = (t >= off) ? sh[t - off] : 0;
        __syncthreads();
        sh[t] += u;
        __syncthreads();
    }
    if (t < N_SCANB) g_boff[t] = sh[t] - v;
}

// scan3 + dinv + cursor init fused
__global__ void scan3_kernel() {
    int i = blockIdx.x * blockDim.x + threadIdx.x;
    if (i < N_NODES) {
        int rs = g_rowstart[i] + g_boff[i / SCAN_BLK];
        g_rowstart[i] = rs;
        g_cursor[i] = rs;
        float deg = 1.0f + (float)(g_pack[i] >> 20) * (1.0f / 16777216.0f);
        g_dinv[i] = rsqrtf(deg);
    }
}

__global__ void fill_kernel(const int* __restrict__ src, const int* __restrict__ dst,
                            const float* __restrict__ ew) {
    int e = blockIdx.x * blockDim.x + threadIdx.x;
    if (e >= N_EDGES) return;
    int s = src[e];
    int d = dst[e];
    float nm = g_dinv[s] * ew[e] * g_dinv[d];
    int slot = atomicAdd(&g_cursor[d], 1);
    g_edge[slot] = make_float2(__int_as_float(s), nm);
}

// ---------------- agg1 + gemm2 fused: 8 warps = 8 nodes per block, MLP-8 ----------------
__global__ __launch_bounds__(256) void agg1_gemm2_kernel(const float* __restrict__ b1,
                                                         const float* __restrict__ W2) {
    __shared__ float hs[8][68];
    __shared__ float ws[64][20];
    const int tid = threadIdx.x;
    const int w = tid >> 5;
    const int lane = tid & 31;
    const int n = blockIdx.x * 8 + w;

#pragma unroll
    for (int i = tid; i < 64 * 20; i += 256) ws[i / 20][i % 20] = W2[i];

    if (n < N_NODES) {
        int i = g_rowstart[n];
        int end = i + g_cnt[n];
        float2 acc = make_float2(0.f, 0.f);
        for (; i + 8 <= end; i += 8) {
            float2 e[8];
#pragma unroll
            for (int j = 0; j < 8; j++) e[j] = g_edge[i + j];
            float2 v[8];
#pragma unroll
            for (int j = 0; j < 8; j++)
                v[j] = __half22float2(g_xw1h[(size_t)__float_as_int(e[j].x) * 32 + lane]);
#pragma unroll
            for (int j = 0; j < 8; j++) {
                acc.x = fmaf(e[j].y, v[j].x, acc.x);
                acc.y = fmaf(e[j].y, v[j].y, acc.y);
            }
        }
        for (; i < end; i++) {
            float2 ep = g_edge[i];
            float2 v = __half22float2(g_xw1h[(size_t)__float_as_int(ep.x) * 32 + lane]);
            acc.x = fmaf(ep.y, v.x, acc.x);
            acc.y = fmaf(ep.y, v.y, acc.y);
        }
        float di = g_dinv[n];
        float dd = di * di;
        float2 xv = __half22float2(g_xw1h[(size_t)n * 32 + lane]);
        float2 bv = *(const float2*)&b1[lane * 2];
        hs[w][lane * 2] = fmaxf(bv.x + dd * xv.x + acc.x, 0.f);
        hs[w][lane * 2 + 1] = fmaxf(bv.y + dd * xv.y + acc.y, 0.f);
    }
    __syncthreads();

    if (tid < 160) {
        int nn = tid / 20;
        int o = tid % 20;
        int node = blockIdx.x * 8 + nn;
        if (node < N_NODES) {
            float acc = 0.f;
#pragma unroll
            for (int k = 0; k < 64; k++) acc = fmaf(hs[nn][k], ws[k][o], acc);
            g_h2h[(size_t)node * 32 + o] = __float2half(acc);
        }
    }
}

// ---------------- agg2 + softmax, MLP-8 ----------------
__global__ __launch_bounds__(256) void agg2_kernel(const float* __restrict__ b2,
                                                   float* __restrict__ out) {
    int warp = (blockIdx.x * blockDim.x + threadIdx.x) >> 5;
    int lane = threadIdx.x & 31;
    if (warp >= N_NODES) return;
    int n = warp;
    int i = g_rowstart[n];
    int end = i + g_cnt[n];
    int col = (lane < F_OUT) ? lane : 0;
    float acc = 0.f;
    for (; i + 8 <= end; i += 8) {
        float2 e[8];
#pragma unroll
        for (int j = 0; j < 8; j++) e[j] = g_edge[i + j];
        float v[8];
#pragma unroll
        for (int j = 0; j < 8; j++)
            v[j] = __half2float(g_h2h[(size_t)__float_as_int(e[j].x) * 32 + col]);
#pragma unroll
        for (int j = 0; j < 8; j++) acc = fmaf(e[j].y, v[j], acc);
    }
    for (; i < end; i++) {
        float2 ep = g_edge[i];
        acc = fmaf(ep.y, __half2float(g_h2h[(size_t)__float_as_int(ep.x) * 32 + col]), acc);
    }
    float di = g_dinv[n];
    float dd = di * di;
    float val = -1e30f;
    if (lane < F_OUT)
        val = b2[lane] + dd * __half2float(g_h2h[(size_t)n * 32 + lane]) + acc;
    float m = val;
#pragma unroll
    for (int o = 16; o > 0; o >>= 1) m = fmaxf(m, __shfl_xor_sync(0xFFFFFFFF, m, o));
    float ex = (lane < F_OUT) ? __expf(val - m) : 0.f;
    float s = ex;
#pragma unroll
    for (int o = 16; o > 0; o >>= 1) s += __shfl_xor_sync(0xFFFFFFFF, s, o);
    if (lane < F_OUT) out[(size_t)n * F_OUT + lane] = ex / s;
}

// ---------------- launch ----------------
extern "C" void kernel_launch(void* const* d_in, const int* in_sizes, int n_in,
                              void* d_out, int out_size) {
    const float* x = (const float*)d_in[0];
    const int* ei = (const int*)d_in[1];
    const float* ew = (const float*)d_in[2];
    const float* W1 = (const float*)d_in[3];
    const float* b1 = (const float*)d_in[4];
    const float* W2 = (const float*)d_in[5];
    const float* b2 = (const float*)d_in[6];
    float* out = (float*)d_out;

    const int* src = ei;
    const int* dst = ei + N_EDGES;

    // one-time infra (created on the uncaptured correctness call; reused during capture)
    static cudaStream_t s2 = nullptr;
    static cudaEvent_t ev_fork = nullptr, ev_join = nullptr;
    if (s2 == nullptr) {
        cudaStreamCreateWithFlags(&s2, cudaStreamNonBlocking);
        cudaEventCreateWithFlags(&ev_fork, cudaEventDisableTiming);
        cudaEventCreateWithFlags(&ev_join, cudaEventDisableTiming);
    }

    // fork: gemm1 on s2, overlapped with the CSR pre-pass on the main stream
    cudaEventRecord(ev_fork, 0);
    cudaStreamWaitEvent(s2, ev_fork, 0);
    gemm1_tc_kernel<<<(N_NODES + 127) / 128, 256, 0, s2>>>(x, W1);
    cudaEventRecord(ev_join, s2);

    // pre-pass chain (main stream)
    init_kernel<<<(N_NODES + 255) / 256, 256>>>();
    deg_accum_kernel<<<(N_EDGES + 255) / 256, 256>>>(dst, ew);
    scan1_kernel<<<N_SCANB, SCAN_BLK>>>();
    scan2_kernel<<<1, 128>>>();
    scan3_kernel<<<(N_NODES + 255) / 256, 256>>>();
    fill_kernel<<<(N_EDGES + 255) / 256, 256>>>(src, dst, ew);

    // join: agg1 needs both fill (main) and gemm1 (s2)
    cudaStreamWaitEvent(0, ev_join, 0);
    agg1_gemm2_kernel<<<(N_NODES + 7) / 8, 256>>>(b1, W2);
    agg2_kernel<<<(N_NODES * 32 + 255) / 256, 256>>>(b2, out);
}